// round 9
// baseline (speedup 1.0000x reference)
#include <cuda_runtime.h>
#include <cuda_bf16.h>
#include <cstdint>
#include <cstddef>

typedef unsigned long long ull;

// Problem constants
#define TT 512
#define BB 32
#define DD 512
#define HH 512

// ---------------------------------------------------------------------------
// Scratch (device globals — no allocations allowed)
// ---------------------------------------------------------------------------
__device__ float g_gi[(size_t)2 * 1536 * (TT * BB)];
__device__ float g_y0[(size_t)TT * BB * 1024];
// hidden state bf16 hi/lo, 4-deep ring, SLICE-major:
// [4 slot][2 dir][64 slice][32 b][8 j]  (one slice = 512 B, contiguous)
__device__ __nv_bfloat16 g_hh[4 * 2 * 64 * 32 * 8];
__device__ __nv_bfloat16 g_hl[4 * 2 * 64 * 32 * 8];
// per-producer dataflow flags: F[dir][slice] = last published step+1
__device__ unsigned g_flags[2 * 64];
__device__ __nv_bfloat16 g_wh[2][1536 * 1024];
__device__ __nv_bfloat16 g_wl[2][1536 * 1024];
__device__ __nv_bfloat16 g_xh[(size_t)16384 * 1024];
__device__ __nv_bfloat16 g_xl[(size_t)16384 * 1024];

// ---------------------------------------------------------------------------
// MMA / ldmatrix macros
// ---------------------------------------------------------------------------
#define MMA_BF16(d, a, b) \
    asm volatile("mma.sync.aligned.m16n8k16.row.col.f32.bf16.bf16.f32 " \
        "{%0,%1,%2,%3}, {%4,%5,%6,%7}, {%8,%9}, {%0,%1,%2,%3};" \
        : "+f"((d)[0]), "+f"((d)[1]), "+f"((d)[2]), "+f"((d)[3]) \
        : "r"((a)[0]), "r"((a)[1]), "r"((a)[2]), "r"((a)[3]), \
          "r"((b)[0]), "r"((b)[1]))

#define LDSM_X4(r, addr) \
    asm volatile("ldmatrix.sync.aligned.m8n8.x4.shared.b16 {%0,%1,%2,%3}, [%4];" \
        : "=r"((r)[0]), "=r"((r)[1]), "=r"((r)[2]), "=r"((r)[3]) : "r"(addr))

#define LDSM_X2(r, addr) \
    asm volatile("ldmatrix.sync.aligned.m8n8.x2.shared.b16 {%0,%1}, [%2];" \
        : "=r"((r)[0]), "=r"((r)[1]) : "r"(addr))

// ---------------------------------------------------------------------------
// split fp32 -> bf16 hi + bf16 lo
// ---------------------------------------------------------------------------
__global__ void split_bf16(const float* __restrict__ x,
                           __nv_bfloat16* __restrict__ hi,
                           __nv_bfloat16* __restrict__ lo, size_t n)
{
    size_t i = (size_t)blockIdx.x * blockDim.x + threadIdx.x;
    size_t stride = (size_t)gridDim.x * blockDim.x;
    for (; i < n; i += stride) {
        float v = x[i];
        __nv_bfloat16 h = __float2bfloat16(v);
        hi[i] = h;
        lo[i] = __float2bfloat16(v - __bfloat162float(h));
    }
}

// ---------------------------------------------------------------------------
// bf16 mma.sync GEMM, 3-pass hi/lo split (unchanged, rounds 6-8 passing).
// ---------------------------------------------------------------------------
#define SKW 40

__global__ void __launch_bounds__(256)
gemm_bf16_mma(const __nv_bfloat16* __restrict__ Wh,
              const __nv_bfloat16* __restrict__ Wl,
              const __nv_bfloat16* __restrict__ Xh,
              const __nv_bfloat16* __restrict__ Xl,
              const float* __restrict__ bias,
              float* __restrict__ C, int K, int ldc)
{
    __shared__ __align__(16) __nv_bfloat16 sWh[128 * SKW];
    __shared__ __align__(16) __nv_bfloat16 sWl[128 * SKW];
    __shared__ __align__(16) __nv_bfloat16 sXh[128 * SKW];
    __shared__ __align__(16) __nv_bfloat16 sXl[128 * SKW];

    const int tid  = threadIdx.x;
    const int wid  = tid >> 5;
    const int lane = tid & 31;
    const int m0   = blockIdx.x * 128;
    const int n0   = blockIdx.y * 128;
    const int wn   = wid >> 2;
    const int wm   = wid & 3;

    float acc[4][4][4];
#pragma unroll
    for (int nt = 0; nt < 4; nt++)
#pragma unroll
        for (int mt = 0; mt < 4; mt++)
#pragma unroll
            for (int e = 0; e < 4; e++) acc[nt][mt][e] = 0.0f;

    const int a_row = wn * 64 + (lane & 15);
    const int a_col = (lane >> 4) * 8;
    const int b_row = wm * 32 + (lane & 7);
    const int b_col = ((lane >> 3) & 1) * 8;
    uint32_t aWh = (uint32_t)__cvta_generic_to_shared(&sWh[a_row * SKW + a_col]);
    uint32_t aWl = (uint32_t)__cvta_generic_to_shared(&sWl[a_row * SKW + a_col]);
    uint32_t aXh = (uint32_t)__cvta_generic_to_shared(&sXh[b_row * SKW + b_col]);
    uint32_t aXl = (uint32_t)__cvta_generic_to_shared(&sXl[b_row * SKW + b_col]);

    for (int k0 = 0; k0 < K; k0 += 32) {
#pragma unroll
        for (int i = 0; i < 2; i++) {
            int idx = tid + i * 256;
            int row = idx >> 2;
            int c   = idx & 3;
            int so  = row * SKW + c * 8;
            size_t gw = (size_t)(n0 + row) * K + k0 + c * 8;
            size_t gx = (size_t)(m0 + row) * K + k0 + c * 8;
            *(uint4*)&sWh[so] = *(const uint4*)(Wh + gw);
            *(uint4*)&sWl[so] = *(const uint4*)(Wl + gw);
            *(uint4*)&sXh[so] = *(const uint4*)(Xh + gx);
            *(uint4*)&sXl[so] = *(const uint4*)(Xl + gx);
        }
        __syncthreads();

#pragma unroll
        for (int kk = 0; kk < 2; kk++) {
            const uint32_t koff = (uint32_t)(kk * 16 * 2);
            uint32_t ah[4][4], al[4][4], bh[4][2], bl[4][2];
#pragma unroll
            for (int nt = 0; nt < 4; nt++) {
                const uint32_t ro = (uint32_t)(nt * 16 * SKW * 2);
                LDSM_X4(ah[nt], aWh + ro + koff);
                LDSM_X4(al[nt], aWl + ro + koff);
            }
#pragma unroll
            for (int mt = 0; mt < 4; mt++) {
                const uint32_t ro = (uint32_t)(mt * 8 * SKW * 2);
                LDSM_X2(bh[mt], aXh + ro + koff);
                LDSM_X2(bl[mt], aXl + ro + koff);
            }
#pragma unroll
            for (int nt = 0; nt < 4; nt++)
#pragma unroll
                for (int mt = 0; mt < 4; mt++) {
                    MMA_BF16(acc[nt][mt], ah[nt], bh[mt]);
                    MMA_BF16(acc[nt][mt], ah[nt], bl[mt]);
                    MMA_BF16(acc[nt][mt], al[nt], bh[mt]);
                }
        }
        __syncthreads();
    }

    const int r0 = lane >> 2;
    const int c0 = (lane & 3) * 2;
#pragma unroll
    for (int nt = 0; nt < 4; nt++) {
        const int nbase = n0 + wn * 64 + nt * 16;
        const float b0 = bias[nbase + r0];
        const float b1 = bias[nbase + 8 + r0];
#pragma unroll
        for (int mt = 0; mt < 4; mt++) {
            const int mbase = m0 + wm * 32 + mt * 8;
            float2 v0, v1;
            v0.x = acc[nt][mt][0] + b0; v0.y = acc[nt][mt][1] + b0;
            v1.x = acc[nt][mt][2] + b1; v1.y = acc[nt][mt][3] + b1;
            *(float2*)(C + (size_t)(nbase + r0) * ldc + mbase + c0) = v0;
            *(float2*)(C + (size_t)(nbase + 8 + r0) * ldc + mbase + c0) = v1;
        }
    }
}

// ---------------------------------------------------------------------------
// Persistent MMA GRU, v3: per-producer dataflow flags (no global barrier),
// 4-deep h ring, slice-major h layout, cp.async staging, 8 warps.
// Grid: 128 CTAs = 2 dirs x 64 slices (8 j each). 256 threads.
// Warp w owns K-eighth (4 ktiles); B frags in 48 regs, loaded once.
// SMEM: A 66,560 B + red[8][2][3][32][4]f 24,576 B = 91,136 B.
// ---------------------------------------------------------------------------
#define RS 520
#define A_ELEMS (32 * RS)
#define RED_OFF (2 * A_ELEMS * 2)
#define MMA_SMEM (RED_OFF + 8 * 2 * 3 * 32 * 16)
#define SLICE_E 256                 // bf16 elems per slice (32 b x 8 j)
#define DSLAB (64 * SLICE_E)        // per (slot,dir) slab in bf16 elems

__global__ __launch_bounds__(256, 1)
void gru_layer_mma(const float* __restrict__ gi,
                   const float* __restrict__ Whh_f,
                   const float* __restrict__ Whh_b,
                   const float* __restrict__ bhh_f,
                   const float* __restrict__ bhh_b,
                   __nv_bfloat16* __restrict__ hh,   // [4][2][64][32][8]
                   __nv_bfloat16* __restrict__ hl,
                   unsigned* __restrict__ flags,     // [2][64]
                   float* __restrict__ y,            // [T][B][1024]
                   float* __restrict__ hid)          // [2][B][H]
{
    extern __shared__ __align__(16) char smraw[];
    __nv_bfloat16* sAh = (__nv_bfloat16*)smraw;
    __nv_bfloat16* sAl = sAh + A_ELEMS;
    float* red = (float*)(smraw + RED_OFF);          // [w][mt][g][lane][4]

    // W init tile aliases the A region (24 rows x RS, hi then lo)
    __nv_bfloat16* sWh = sAh;
    __nv_bfloat16* sWl = sAh + 24 * RS;

    const int tid  = threadIdx.x;
    const int wid  = tid >> 5;
    const int lane = tid & 31;
    const int dir  = (int)(blockIdx.x >> 6);
    const int jb   = (int)(blockIdx.x & 63);
    const int j0   = jb * 8;

    const float* Whh = dir ? Whh_b : Whh_f;
    const float* bhh = dir ? bhh_b : bhh_f;

    // ---- stage Whh tile (24 rows x 512) hi/lo split into smem ----
    for (int i = tid; i < 24 * 128; i += 256) {
        int rr = i >> 7;          // 0..23  (= g*8 + jj)
        int c4 = i & 127;
        int g = rr >> 3, jj = rr & 7;
        int grow = g * 512 + j0 + jj;
        float4 v = *(const float4*)(Whh + (size_t)grow * 512 + c4 * 4);
        int so = rr * RS + c4 * 4;
        float vv[4] = {v.x, v.y, v.z, v.w};
#pragma unroll
        for (int e = 0; e < 4; e++) {
            __nv_bfloat16 h = __float2bfloat16(vv[e]);
            sWh[so + e] = h;
            sWl[so + e] = __float2bfloat16(vv[e] - __bfloat162float(h));
        }
    }
    __syncthreads();

    // ---- hoist B fragments into registers: [4 kt][3 g][hi/lo][2] ----
    uint32_t bh[4][3][2], bl[4][3][2];
    {
        const int brow = (lane & 7);
        const int bcol = ((lane >> 3) & 1) * 8;
#pragma unroll
        for (int kt = 0; kt < 4; kt++) {
            const uint32_t koff = (uint32_t)((wid * 4 + kt) * 32);
#pragma unroll
            for (int g = 0; g < 3; g++) {
                uint32_t ah_ = (uint32_t)__cvta_generic_to_shared(
                    sWh + (g * 8 + brow) * RS + bcol) + koff;
                uint32_t al_ = (uint32_t)__cvta_generic_to_shared(
                    sWl + (g * 8 + brow) * RS + bcol) + koff;
                LDSM_X2(bh[kt][g], ah_);
                LDSM_X2(bl[kt][g], al_);
            }
        }
    }
    __syncthreads();   // W region dead; A buffers may now be written

    // ---- per-lane geometry ----
    uint32_t aAh[2], aAl[2];
#pragma unroll
    for (int mt = 0; mt < 2; mt++) {
        const int arow = mt * 16 + (lane & 15);
        const int acol = (lane >> 4) * 8;
        aAh[mt] = (uint32_t)__cvta_generic_to_shared(sAh + arow * RS + acol);
        aAl[mt] = (uint32_t)__cvta_generic_to_shared(sAl + arow * RS + acol);
    }
    // staging destinations (byte addrs): row=lane, col = p*8 bf16
    const uint32_t stH = (uint32_t)__cvta_generic_to_shared(sAh + lane * RS);
    const uint32_t stL = (uint32_t)__cvta_generic_to_shared(sAl + lane * RS);

    // gates ownership (warps 0/1): mt = wid
    const int gm  = wid;
    const int b0  = gm * 16 + (lane >> 2);
    const int b1  = b0 + 8;
    const int j   = j0 + 2 * (lane & 3);

    const float br0 = bhh[j],          br1 = bhh[j + 1];
    const float bz0 = bhh[HH + j],     bz1 = bhh[HH + j + 1];
    const float bn0 = bhh[2 * HH + j], bn1 = bhh[2 * HH + j + 1];

    const float* gb[3][2];
#pragma unroll
    for (int g = 0; g < 3; g++) {
#pragma unroll
        for (int q = 0; q < 2; q++)
            gb[g][q] = gi + ((size_t)dir * 1536 + g * 512 + j + q) * (size_t)(TT * BB);
    }

    unsigned* Fd = flags + dir * 64;
    unsigned* myflag = Fd + jb;

    float hp[4] = {0.0f, 0.0f, 0.0f, 0.0f};

    for (int s = 0; s < TT; s++) {
        const int t = dir ? (TT - 1 - s) : s;

        // ---- gi prefetch (warps 0/1), before the poll ----
        float pre[3][4];
        if (wid < 2) {
#pragma unroll
            for (int g = 0; g < 3; g++) {
                pre[g][0] = __ldcg(gb[g][0] + t * BB + b0);
                pre[g][1] = __ldcg(gb[g][1] + t * BB + b0);
                pre[g][2] = __ldcg(gb[g][0] + t * BB + b1);
                pre[g][3] = __ldcg(gb[g][1] + t * BB + b1);
            }
        }

        // ---- poll all 64 producer flags (warp-parallel) ----
        {
            const unsigned target = (unsigned)s;
            for (;;) {
                unsigned v0, v1;
                asm volatile("ld.acquire.gpu.global.u32 %0, [%1];"
                             : "=r"(v0) : "l"(Fd + lane) : "memory");
                asm volatile("ld.acquire.gpu.global.u32 %0, [%1];"
                             : "=r"(v1) : "l"(Fd + 32 + lane) : "memory");
                if (__all_sync(0xFFFFFFFFu, (v0 >= target) && (v1 >= target)))
                    break;
            }
        }

        // ---- cp.async stage this warp's 8 slices (hi + lo) ----
        {
            const size_t sb = ((size_t)(s & 3) * 2 + dir) * DSLAB;
            const __nv_bfloat16* srch = hh + sb;
            const __nv_bfloat16* srcl = hl + sb;
#pragma unroll
            for (int i = 0; i < 8; i++) {
                const int p = wid * 8 + i;
                const __nv_bfloat16* gh = srch + p * SLICE_E + lane * 8;
                const __nv_bfloat16* gl = srcl + p * SLICE_E + lane * 8;
                const uint32_t dh = stH + (uint32_t)(p * 16);
                const uint32_t dl = stL + (uint32_t)(p * 16);
                asm volatile("cp.async.cg.shared.global [%0], [%1], 16;"
                             :: "r"(dh), "l"(gh) : "memory");
                asm volatile("cp.async.cg.shared.global [%0], [%1], 16;"
                             :: "r"(dl), "l"(gl) : "memory");
            }
            asm volatile("cp.async.commit_group;" ::: "memory");
            asm volatile("cp.async.wait_group 0;" ::: "memory");
        }
        __syncthreads();

        // ---- MMA over this warp's 4 ktiles ----
        float acc[2][3][4];
#pragma unroll
        for (int mt = 0; mt < 2; mt++)
#pragma unroll
            for (int g = 0; g < 3; g++)
#pragma unroll
                for (int e = 0; e < 4; e++) acc[mt][g][e] = 0.0f;

#pragma unroll
        for (int kt = 0; kt < 4; kt++) {
            const uint32_t koff = (uint32_t)((wid * 4 + kt) * 32);
#pragma unroll
            for (int mt = 0; mt < 2; mt++) {
                uint32_t ah[4], al[4];
                LDSM_X4(ah, aAh[mt] + koff);
                LDSM_X4(al, aAl[mt] + koff);
#pragma unroll
                for (int g = 0; g < 3; g++) {
                    MMA_BF16(acc[mt][g], ah, bh[kt][g]);
                    MMA_BF16(acc[mt][g], ah, bl[kt][g]);
                    MMA_BF16(acc[mt][g], al, bh[kt][g]);
                }
            }
        }

        // ---- cross-warp K-reduction via smem ----
#pragma unroll
        for (int mt = 0; mt < 2; mt++)
#pragma unroll
            for (int g = 0; g < 3; g++) {
                float4 v;
                v.x = acc[mt][g][0]; v.y = acc[mt][g][1];
                v.z = acc[mt][g][2]; v.w = acc[mt][g][3];
                *(float4*)(red + (((wid * 2 + mt) * 3 + g) * 32 + lane) * 4) = v;
            }
        __syncthreads();

        // ---- gates + publish (warps 0/1) ----
        float hn[4];
        if (wid < 2) {
            float tot[3][4];
#pragma unroll
            for (int g = 0; g < 3; g++) {
                tot[g][0] = 0.0f; tot[g][1] = 0.0f;
                tot[g][2] = 0.0f; tot[g][3] = 0.0f;
#pragma unroll
                for (int w = 0; w < 8; w++) {
                    float4 v = *(float4*)(red + (((w * 2 + gm) * 3 + g) * 32 + lane) * 4);
                    tot[g][0] += v.x; tot[g][1] += v.y;
                    tot[g][2] += v.z; tot[g][3] += v.w;
                }
            }

            const float brj[2] = {br0, br1}, bzj[2] = {bz0, bz1}, bnj[2] = {bn0, bn1};
#pragma unroll
            for (int c = 0; c < 4; c++) {
                const int q = c & 1;
                const float ar = tot[0][c] + brj[q];
                const float az = tot[1][c] + bzj[q];
                const float an = tot[2][c] + bnj[q];
                const float r = 1.0f / (1.0f + expf(-(pre[0][c] + ar)));
                const float z = 1.0f / (1.0f + expf(-(pre[1][c] + az)));
                const float n = tanhf(pre[2][c] + r * an);
                hn[c] = (1.0f - z) * n + z * hp[c];
                hp[c] = hn[c];
            }

            // publish h slice (slice-major layout, slot s+1)
            const size_t ob = ((size_t)((s + 1) & 3) * 2 + dir) * DSLAB
                            + (size_t)jb * SLICE_E;
            const int off = 2 * (lane & 3);
            __nv_bfloat162 h2, l2;
            h2.x = __float2bfloat16(hn[0]);
            h2.y = __float2bfloat16(hn[1]);
            l2.x = __float2bfloat16(hn[0] - __bfloat162float(h2.x));
            l2.y = __float2bfloat16(hn[1] - __bfloat162float(h2.y));
            *(__nv_bfloat162*)(hh + ob + b0 * 8 + off) = h2;
            *(__nv_bfloat162*)(hl + ob + b0 * 8 + off) = l2;
            h2.x = __float2bfloat16(hn[2]);
            h2.y = __float2bfloat16(hn[3]);
            l2.x = __float2bfloat16(hn[2] - __bfloat162float(h2.x));
            l2.y = __float2bfloat16(hn[3] - __bfloat162float(h2.y));
            *(__nv_bfloat162*)(hh + ob + b1 * 8 + off) = h2;
            *(__nv_bfloat162*)(hl + ob + b1 * 8 + off) = l2;
        }

        // ---- release our flag, then off-path y/hid stores ----
        __syncthreads();
        if (tid == 0) {
            __threadfence();
            asm volatile("st.release.gpu.global.u32 [%0], %1;"
                         :: "l"(myflag), "r"((unsigned)(s + 1)) : "memory");
        }
        if (wid < 2) {
            float2 y2;
            y2.x = hn[0]; y2.y = hn[1];
            *(float2*)(y + ((size_t)t * BB + b0) * 1024 + (size_t)dir * HH + j) = y2;
            y2.x = hn[2]; y2.y = hn[3];
            *(float2*)(y + ((size_t)t * BB + b1) * 1024 + (size_t)dir * HH + j) = y2;
            if (s == TT - 1) {
                float2 q2;
                q2.x = hn[0]; q2.y = hn[1];
                *(float2*)(hid + ((size_t)dir * BB + b0) * HH + j) = q2;
                q2.x = hn[2]; q2.y = hn[3];
                *(float2*)(hid + ((size_t)dir * BB + b1) * HH + j) = q2;
            }
        }
    }
}

// ---------------------------------------------------------------------------
// Launch
// ---------------------------------------------------------------------------
extern "C" void kernel_launch(void* const* d_in, const int* in_sizes, int n_in,
                              void* d_out, int out_size)
{
    (void)in_sizes; (void)n_in; (void)out_size;

    const float* x     = (const float*)d_in[0];
    const float* Wih0f = (const float*)d_in[1];
    const float* Whh0f = (const float*)d_in[2];
    const float* bih0f = (const float*)d_in[3];
    const float* bhh0f = (const float*)d_in[4];
    const float* Wih0b = (const float*)d_in[5];
    const float* Whh0b = (const float*)d_in[6];
    const float* bih0b = (const float*)d_in[7];
    const float* bhh0b = (const float*)d_in[8];
    const float* Wih1f = (const float*)d_in[9];
    const float* Whh1f = (const float*)d_in[10];
    const float* bih1f = (const float*)d_in[11];
    const float* bhh1f = (const float*)d_in[12];
    const float* Wih1b = (const float*)d_in[13];
    const float* Whh1b = (const float*)d_in[14];
    const float* bih1b = (const float*)d_in[15];
    const float* bhh1b = (const float*)d_in[16];

    float* out = (float*)d_out;
    const size_t Y_ELEMS = (size_t)TT * BB * 1024;
    float* hid0 = out + Y_ELEMS;
    float* hid1 = out + Y_ELEMS + 2 * BB * HH;

    float* gi = nullptr; cudaGetSymbolAddress((void**)&gi, g_gi);
    float* y0 = nullptr; cudaGetSymbolAddress((void**)&y0, g_y0);
    __nv_bfloat16* hh = nullptr; cudaGetSymbolAddress((void**)&hh, g_hh);
    __nv_bfloat16* hl = nullptr; cudaGetSymbolAddress((void**)&hl, g_hl);
    unsigned* flags = nullptr; cudaGetSymbolAddress((void**)&flags, g_flags);
    __nv_bfloat16* wh = nullptr; cudaGetSymbolAddress((void**)&wh, g_wh);
    __nv_bfloat16* wl = nullptr; cudaGetSymbolAddress((void**)&wl, g_wl);
    __nv_bfloat16* xh = nullptr; cudaGetSymbolAddress((void**)&xh, g_xh);
    __nv_bfloat16* xl = nullptr; cudaGetSymbolAddress((void**)&xl, g_xl);

    cudaFuncSetAttribute(gru_layer_mma,
                         cudaFuncAttributeMaxDynamicSharedMemorySize, MMA_SMEM);

    const size_t M = (size_t)TT * BB;            // 16384
    const size_t DIROFF = (size_t)1536 * M;
    const size_t WSLAB = (size_t)1536 * 1024;
    const dim3 ggrid(128, 12);
    const size_t HBYTES = (size_t)4 * 2 * 64 * 32 * 8 * sizeof(__nv_bfloat16);

    // ---------------- layer 0 (K = 512) ----------------
    split_bf16<<<512, 256>>>(Wih0f, wh,          wl,          (size_t)1536 * DD);
    split_bf16<<<512, 256>>>(Wih0b, wh + WSLAB,  wl + WSLAB,  (size_t)1536 * DD);
    split_bf16<<<1024, 256>>>(x,    xh,          xl,          M * DD);

    gemm_bf16_mma<<<ggrid, 256>>>(wh,         wl,         xh, xl, bih0f,
                                  gi,          DD, (int)M);
    gemm_bf16_mma<<<ggrid, 256>>>(wh + WSLAB, wl + WSLAB, xh, xl, bih0b,
                                  gi + DIROFF, DD, (int)M);

    cudaMemsetAsync(hh, 0, HBYTES);
    cudaMemsetAsync(hl, 0, HBYTES);
    cudaMemsetAsync(flags, 0, 2 * 64 * sizeof(unsigned));

    gru_layer_mma<<<128, 256, MMA_SMEM>>>(
        gi, Whh0f, Whh0b, bhh0f, bhh0b, hh, hl, flags, y0, hid0);

    // ---------------- layer 1 (K = 1024) ----------------
    split_bf16<<<512, 256>>>(Wih1f, wh,          wl,          (size_t)1536 * 1024);
    split_bf16<<<512, 256>>>(Wih1b, wh + WSLAB,  wl + WSLAB,  (size_t)1536 * 1024);
    split_bf16<<<1024, 256>>>(y0,   xh,          xl,          M * 1024);

    gemm_bf16_mma<<<ggrid, 256>>>(wh,         wl,         xh, xl, bih1f,
                                  gi,          1024, (int)M);
    gemm_bf16_mma<<<ggrid, 256>>>(wh + WSLAB, wl + WSLAB, xh, xl, bih1b,
                                  gi + DIROFF, 1024, (int)M);

    cudaMemsetAsync(hh, 0, HBYTES);
    cudaMemsetAsync(hl, 0, HBYTES);
    cudaMemsetAsync(flags, 0, 2 * 64 * sizeof(unsigned));

    gru_layer_mma<<<128, 256, MMA_SMEM>>>(
        gi, Whh1f, Whh1b, bhh1f, bhh1b, hh, hl, flags, out, hid1);
}

// round 12
// speedup vs baseline: 1.3938x; 1.3938x over previous
#include <cuda_runtime.h>
#include <cuda_bf16.h>
#include <cstdint>
#include <cstddef>

typedef unsigned long long ull;

// Problem constants
#define TT 512
#define BB 32
#define DD 512
#define HH 512

// ---------------------------------------------------------------------------
// Scratch (device globals — no allocations allowed)
// ---------------------------------------------------------------------------
__device__ float g_gi[(size_t)2 * 1536 * (TT * BB)];
__device__ float g_y0[(size_t)TT * BB * 1024];
// hidden state bf16 hi/lo, 2-slot ping-pong, SLICE-major:
// [2 slot][2 dir][64 slice][32 b][8 j]  (one slice = 512 B, contiguous)
__device__ __nv_bfloat16 g_hh[2 * 2 * 64 * 32 * 8];
__device__ __nv_bfloat16 g_hl[2 * 2 * 64 * 32 * 8];
// barrier state (rounds 3-8 proven): arrival counter + release flag per dir
__device__ unsigned g_cnt[2];
__device__ unsigned g_flag[2];
__device__ __nv_bfloat16 g_wh[2][1536 * 1024];
__device__ __nv_bfloat16 g_wl[2][1536 * 1024];
__device__ __nv_bfloat16 g_xh[(size_t)16384 * 1024];
__device__ __nv_bfloat16 g_xl[(size_t)16384 * 1024];

// ---------------------------------------------------------------------------
// MMA / ldmatrix macros
// ---------------------------------------------------------------------------
#define MMA_BF16(d, a, b) \
    asm volatile("mma.sync.aligned.m16n8k16.row.col.f32.bf16.bf16.f32 " \
        "{%0,%1,%2,%3}, {%4,%5,%6,%7}, {%8,%9}, {%0,%1,%2,%3};" \
        : "+f"((d)[0]), "+f"((d)[1]), "+f"((d)[2]), "+f"((d)[3]) \
        : "r"((a)[0]), "r"((a)[1]), "r"((a)[2]), "r"((a)[3]), \
          "r"((b)[0]), "r"((b)[1]))

#define LDSM_X4(r, addr) \
    asm volatile("ldmatrix.sync.aligned.m8n8.x4.shared.b16 {%0,%1,%2,%3}, [%4];" \
        : "=r"((r)[0]), "=r"((r)[1]), "=r"((r)[2]), "=r"((r)[3]) : "r"(addr))

#define LDSM_X2(r, addr) \
    asm volatile("ldmatrix.sync.aligned.m8n8.x2.shared.b16 {%0,%1}, [%2];" \
        : "=r"((r)[0]), "=r"((r)[1]) : "r"(addr))

// ---------------------------------------------------------------------------
// split fp32 -> bf16 hi + bf16 lo
// ---------------------------------------------------------------------------
__global__ void split_bf16(const float* __restrict__ x,
                           __nv_bfloat16* __restrict__ hi,
                           __nv_bfloat16* __restrict__ lo, size_t n)
{
    size_t i = (size_t)blockIdx.x * blockDim.x + threadIdx.x;
    size_t stride = (size_t)gridDim.x * blockDim.x;
    for (; i < n; i += stride) {
        float v = x[i];
        __nv_bfloat16 h = __float2bfloat16(v);
        hi[i] = h;
        lo[i] = __float2bfloat16(v - __bfloat162float(h));
    }
}

// ---------------------------------------------------------------------------
// bf16 mma.sync GEMM, 3-pass hi/lo split (unchanged, rounds 6-8 passing).
// ---------------------------------------------------------------------------
#define SKW 40

__global__ void __launch_bounds__(256)
gemm_bf16_mma(const __nv_bfloat16* __restrict__ Wh,
              const __nv_bfloat16* __restrict__ Wl,
              const __nv_bfloat16* __restrict__ Xh,
              const __nv_bfloat16* __restrict__ Xl,
              const float* __restrict__ bias,
              float* __restrict__ C, int K, int ldc)
{
    __shared__ __align__(16) __nv_bfloat16 sWh[128 * SKW];
    __shared__ __align__(16) __nv_bfloat16 sWl[128 * SKW];
    __shared__ __align__(16) __nv_bfloat16 sXh[128 * SKW];
    __shared__ __align__(16) __nv_bfloat16 sXl[128 * SKW];

    const int tid  = threadIdx.x;
    const int wid  = tid >> 5;
    const int lane = tid & 31;
    const int m0   = blockIdx.x * 128;
    const int n0   = blockIdx.y * 128;
    const int wn   = wid >> 2;
    const int wm   = wid & 3;

    float acc[4][4][4];
#pragma unroll
    for (int nt = 0; nt < 4; nt++)
#pragma unroll
        for (int mt = 0; mt < 4; mt++)
#pragma unroll
            for (int e = 0; e < 4; e++) acc[nt][mt][e] = 0.0f;

    const int a_row = wn * 64 + (lane & 15);
    const int a_col = (lane >> 4) * 8;
    const int b_row = wm * 32 + (lane & 7);
    const int b_col = ((lane >> 3) & 1) * 8;
    uint32_t aWh = (uint32_t)__cvta_generic_to_shared(&sWh[a_row * SKW + a_col]);
    uint32_t aWl = (uint32_t)__cvta_generic_to_shared(&sWl[a_row * SKW + a_col]);
    uint32_t aXh = (uint32_t)__cvta_generic_to_shared(&sXh[b_row * SKW + b_col]);
    uint32_t aXl = (uint32_t)__cvta_generic_to_shared(&sXl[b_row * SKW + b_col]);

    for (int k0 = 0; k0 < K; k0 += 32) {
#pragma unroll
        for (int i = 0; i < 2; i++) {
            int idx = tid + i * 256;
            int row = idx >> 2;
            int c   = idx & 3;
            int so  = row * SKW + c * 8;
            size_t gw = (size_t)(n0 + row) * K + k0 + c * 8;
            size_t gx = (size_t)(m0 + row) * K + k0 + c * 8;
            *(uint4*)&sWh[so] = *(const uint4*)(Wh + gw);
            *(uint4*)&sWl[so] = *(const uint4*)(Wl + gw);
            *(uint4*)&sXh[so] = *(const uint4*)(Xh + gx);
            *(uint4*)&sXl[so] = *(const uint4*)(Xl + gx);
        }
        __syncthreads();

#pragma unroll
        for (int kk = 0; kk < 2; kk++) {
            const uint32_t koff = (uint32_t)(kk * 16 * 2);
            uint32_t ah[4][4], al[4][4], bh[4][2], bl[4][2];
#pragma unroll
            for (int nt = 0; nt < 4; nt++) {
                const uint32_t ro = (uint32_t)(nt * 16 * SKW * 2);
                LDSM_X4(ah[nt], aWh + ro + koff);
                LDSM_X4(al[nt], aWl + ro + koff);
            }
#pragma unroll
            for (int mt = 0; mt < 4; mt++) {
                const uint32_t ro = (uint32_t)(mt * 8 * SKW * 2);
                LDSM_X2(bh[mt], aXh + ro + koff);
                LDSM_X2(bl[mt], aXl + ro + koff);
            }
#pragma unroll
            for (int nt = 0; nt < 4; nt++)
#pragma unroll
                for (int mt = 0; mt < 4; mt++) {
                    MMA_BF16(acc[nt][mt], ah[nt], bh[mt]);
                    MMA_BF16(acc[nt][mt], ah[nt], bl[mt]);
                    MMA_BF16(acc[nt][mt], al[nt], bh[mt]);
                }
        }
        __syncthreads();
    }

    const int r0 = lane >> 2;
    const int c0 = (lane & 3) * 2;
#pragma unroll
    for (int nt = 0; nt < 4; nt++) {
        const int nbase = n0 + wn * 64 + nt * 16;
        const float b0 = bias[nbase + r0];
        const float b1 = bias[nbase + 8 + r0];
#pragma unroll
        for (int mt = 0; mt < 4; mt++) {
            const int mbase = m0 + wm * 32 + mt * 8;
            float2 v0, v1;
            v0.x = acc[nt][mt][0] + b0; v0.y = acc[nt][mt][1] + b0;
            v1.x = acc[nt][mt][2] + b1; v1.y = acc[nt][mt][3] + b1;
            *(float2*)(C + (size_t)(nbase + r0) * ldc + mbase + c0) = v0;
            *(float2*)(C + (size_t)(nbase + 8 + r0) * ldc + mbase + c0) = v1;
        }
    }
}

// ---------------------------------------------------------------------------
// Persistent MMA GRU, v5 (RESUBMIT of round 11 — failure attributed to infra:
// identical design components passed separately in rounds 8 and 9).
// Round-8 proven global barrier (counter + sense flag, tid0-only spin) +
// round-9 intra-CTA engine (256 threads, 8 K-specialized warps w/ register
// B-fragments, slice-major h, cp.async staging).
// Grid: 128 CTAs = 2 dirs x 64 slices (8 j each). 256 threads.
// SMEM: A 66,560 B + red[8][2][3][32][4]f 24,576 B = 91,136 B.
// 128 CTAs co-resident (>= 1 CTA/SM on 148 SMs) -> spin barrier safe.
// ---------------------------------------------------------------------------
#define RS 520
#define A_ELEMS (32 * RS)
#define RED_OFF (2 * A_ELEMS * 2)
#define MMA_SMEM (RED_OFF + 8 * 2 * 3 * 32 * 16)
#define SLICE_E 256                 // bf16 elems per slice (32 b x 8 j)
#define DSLAB (64 * SLICE_E)        // per (slot,dir) slab in bf16 elems
#define NCD 64                      // CTAs per direction

__global__ __launch_bounds__(256, 1)
void gru_layer_mma(const float* __restrict__ gi,
                   const float* __restrict__ Whh_f,
                   const float* __restrict__ Whh_b,
                   const float* __restrict__ bhh_f,
                   const float* __restrict__ bhh_b,
                   __nv_bfloat16* __restrict__ hh,   // [2][2][64][32][8]
                   __nv_bfloat16* __restrict__ hl,
                   unsigned* __restrict__ cnt,       // [2], zeroed pre-launch
                   unsigned* __restrict__ flag,      // [2], zeroed pre-launch
                   float* __restrict__ y,            // [T][B][1024]
                   float* __restrict__ hid)          // [2][B][H]
{
    extern __shared__ __align__(16) char smraw[];
    __nv_bfloat16* sAh = (__nv_bfloat16*)smraw;
    __nv_bfloat16* sAl = sAh + A_ELEMS;
    float* red = (float*)(smraw + RED_OFF);          // [w][mt][g][lane][4]

    // W init tile aliases the A region (24 rows x RS, hi then lo)
    __nv_bfloat16* sWh = sAh;
    __nv_bfloat16* sWl = sAh + 24 * RS;

    const int tid  = threadIdx.x;
    const int wid  = tid >> 5;
    const int lane = tid & 31;
    const int dir  = (int)(blockIdx.x >> 6);
    const int jb   = (int)(blockIdx.x & 63);
    const int j0   = jb * 8;

    const float* Whh = dir ? Whh_b : Whh_f;
    const float* bhh = dir ? bhh_b : bhh_f;

    // ---- stage Whh tile (24 rows x 512) hi/lo split into smem ----
    for (int i = tid; i < 24 * 128; i += 256) {
        int rr = i >> 7;          // 0..23  (= g*8 + jj)
        int c4 = i & 127;
        int g = rr >> 3, jj = rr & 7;
        int grow = g * 512 + j0 + jj;
        float4 v = *(const float4*)(Whh + (size_t)grow * 512 + c4 * 4);
        int so = rr * RS + c4 * 4;
        float vv[4] = {v.x, v.y, v.z, v.w};
#pragma unroll
        for (int e = 0; e < 4; e++) {
            __nv_bfloat16 h = __float2bfloat16(vv[e]);
            sWh[so + e] = h;
            sWl[so + e] = __float2bfloat16(vv[e] - __bfloat162float(h));
        }
    }
    __syncthreads();

    // ---- hoist B fragments into registers: [4 kt][3 g][hi/lo][2] ----
    uint32_t bh[4][3][2], bl[4][3][2];
    {
        const int brow = (lane & 7);
        const int bcol = ((lane >> 3) & 1) * 8;
#pragma unroll
        for (int kt = 0; kt < 4; kt++) {
            const uint32_t koff = (uint32_t)((wid * 4 + kt) * 32);
#pragma unroll
            for (int g = 0; g < 3; g++) {
                uint32_t ah_ = (uint32_t)__cvta_generic_to_shared(
                    sWh + (g * 8 + brow) * RS + bcol) + koff;
                uint32_t al_ = (uint32_t)__cvta_generic_to_shared(
                    sWl + (g * 8 + brow) * RS + bcol) + koff;
                LDSM_X2(bh[kt][g], ah_);
                LDSM_X2(bl[kt][g], al_);
            }
        }
    }
    __syncthreads();   // W region dead; A buffers may now be written

    // ---- per-lane geometry ----
    uint32_t aAh[2], aAl[2];
#pragma unroll
    for (int mt = 0; mt < 2; mt++) {
        const int arow = mt * 16 + (lane & 15);
        const int acol = (lane >> 4) * 8;
        aAh[mt] = (uint32_t)__cvta_generic_to_shared(sAh + arow * RS + acol);
        aAl[mt] = (uint32_t)__cvta_generic_to_shared(sAl + arow * RS + acol);
    }
    // staging destinations (byte addrs): row=lane, col = p*8 bf16
    const uint32_t stH = (uint32_t)__cvta_generic_to_shared(sAh + lane * RS);
    const uint32_t stL = (uint32_t)__cvta_generic_to_shared(sAl + lane * RS);

    // gates ownership (warps 0/1): mt = wid
    const int gm  = wid;
    const int b0  = gm * 16 + (lane >> 2);
    const int b1  = b0 + 8;
    const int j   = j0 + 2 * (lane & 3);

    const float br0 = bhh[j],          br1 = bhh[j + 1];
    const float bz0 = bhh[HH + j],     bz1 = bhh[HH + j + 1];
    const float bn0 = bhh[2 * HH + j], bn1 = bhh[2 * HH + j + 1];

    const float* gb[3][2];
#pragma unroll
    for (int g = 0; g < 3; g++) {
#pragma unroll
        for (int q = 0; q < 2; q++)
            gb[g][q] = gi + ((size_t)dir * 1536 + g * 512 + j + q) * (size_t)(TT * BB);
    }

    unsigned* mycnt  = cnt + dir;
    unsigned* myflag = flag + dir;

    float hp[4] = {0.0f, 0.0f, 0.0f, 0.0f};

    for (int s = 0; s < TT; s++) {
        const int t = dir ? (TT - 1 - s) : s;

        // ---- gi prefetch (warps 0/1) ----
        float pre[3][4];
        if (wid < 2) {
#pragma unroll
            for (int g = 0; g < 3; g++) {
                pre[g][0] = __ldcg(gb[g][0] + t * BB + b0);
                pre[g][1] = __ldcg(gb[g][1] + t * BB + b0);
                pre[g][2] = __ldcg(gb[g][0] + t * BB + b1);
                pre[g][3] = __ldcg(gb[g][1] + t * BB + b1);
            }
        }

        // ---- cp.async stage this warp's 8 slices (hi + lo) ----
        // (slot s&1 is fully published: end-of-step-(s-1) global barrier)
        {
            const size_t sb = ((size_t)(s & 1) * 2 + dir) * DSLAB;
            const __nv_bfloat16* srch = hh + sb;
            const __nv_bfloat16* srcl = hl + sb;
#pragma unroll
            for (int i = 0; i < 8; i++) {
                const int p = wid * 8 + i;
                const __nv_bfloat16* gh = srch + p * SLICE_E + lane * 8;
                const __nv_bfloat16* gl = srcl + p * SLICE_E + lane * 8;
                const uint32_t dh = stH + (uint32_t)(p * 16);
                const uint32_t dl = stL + (uint32_t)(p * 16);
                asm volatile("cp.async.cg.shared.global [%0], [%1], 16;"
                             :: "r"(dh), "l"(gh) : "memory");
                asm volatile("cp.async.cg.shared.global [%0], [%1], 16;"
                             :: "r"(dl), "l"(gl) : "memory");
            }
            asm volatile("cp.async.commit_group;" ::: "memory");
            asm volatile("cp.async.wait_group 0;" ::: "memory");
        }
        __syncthreads();

        // ---- MMA over this warp's 4 ktiles ----
        float acc[2][3][4];
#pragma unroll
        for (int mt = 0; mt < 2; mt++)
#pragma unroll
            for (int g = 0; g < 3; g++)
#pragma unroll
                for (int e = 0; e < 4; e++) acc[mt][g][e] = 0.0f;

#pragma unroll
        for (int kt = 0; kt < 4; kt++) {
            const uint32_t koff = (uint32_t)((wid * 4 + kt) * 32);
#pragma unroll
            for (int mt = 0; mt < 2; mt++) {
                uint32_t ah[4], al[4];
                LDSM_X4(ah, aAh[mt] + koff);
                LDSM_X4(al, aAl[mt] + koff);
#pragma unroll
                for (int g = 0; g < 3; g++) {
                    MMA_BF16(acc[mt][g], ah, bh[kt][g]);
                    MMA_BF16(acc[mt][g], ah, bl[kt][g]);
                    MMA_BF16(acc[mt][g], al, bh[kt][g]);
                }
            }
        }

        // ---- cross-warp K-reduction via smem ----
#pragma unroll
        for (int mt = 0; mt < 2; mt++)
#pragma unroll
            for (int g = 0; g < 3; g++) {
                float4 v;
                v.x = acc[mt][g][0]; v.y = acc[mt][g][1];
                v.z = acc[mt][g][2]; v.w = acc[mt][g][3];
                *(float4*)(red + (((wid * 2 + mt) * 3 + g) * 32 + lane) * 4) = v;
            }
        __syncthreads();

        // ---- gates + publish (warps 0/1) ----
        float hn[4];
        if (wid < 2) {
            float tot[3][4];
#pragma unroll
            for (int g = 0; g < 3; g++) {
                tot[g][0] = 0.0f; tot[g][1] = 0.0f;
                tot[g][2] = 0.0f; tot[g][3] = 0.0f;
#pragma unroll
                for (int w = 0; w < 8; w++) {
                    float4 v = *(float4*)(red + (((w * 2 + gm) * 3 + g) * 32 + lane) * 4);
                    tot[g][0] += v.x; tot[g][1] += v.y;
                    tot[g][2] += v.z; tot[g][3] += v.w;
                }
            }

            const float brj[2] = {br0, br1}, bzj[2] = {bz0, bz1}, bnj[2] = {bn0, bn1};
#pragma unroll
            for (int c = 0; c < 4; c++) {
                const int q = c & 1;
                const float ar = tot[0][c] + brj[q];
                const float az = tot[1][c] + bzj[q];
                const float an = tot[2][c] + bnj[q];
                const float r = 1.0f / (1.0f + expf(-(pre[0][c] + ar)));
                const float z = 1.0f / (1.0f + expf(-(pre[1][c] + az)));
                const float n = tanhf(pre[2][c] + r * an);
                hn[c] = (1.0f - z) * n + z * hp[c];
                hp[c] = hn[c];
            }

            // publish h slice (slice-major layout, slot (s+1)&1)
            const size_t ob = ((size_t)((s + 1) & 1) * 2 + dir) * DSLAB
                            + (size_t)jb * SLICE_E;
            const int off = 2 * (lane & 3);
            __nv_bfloat162 h2, l2;
            h2.x = __float2bfloat16(hn[0]);
            h2.y = __float2bfloat16(hn[1]);
            l2.x = __float2bfloat16(hn[0] - __bfloat162float(h2.x));
            l2.y = __float2bfloat16(hn[1] - __bfloat162float(h2.y));
            *(__nv_bfloat162*)(hh + ob + b0 * 8 + off) = h2;
            *(__nv_bfloat162*)(hl + ob + b0 * 8 + off) = l2;
            h2.x = __float2bfloat16(hn[2]);
            h2.y = __float2bfloat16(hn[3]);
            l2.x = __float2bfloat16(hn[2] - __bfloat162float(h2.x));
            l2.y = __float2bfloat16(hn[3] - __bfloat162float(h2.y));
            *(__nv_bfloat162*)(hh + ob + b1 * 8 + off) = h2;
            *(__nv_bfloat162*)(hl + ob + b1 * 8 + off) = l2;
        }

        // ---- per-direction global barrier (rounds 3-8 proven) ----
        __syncthreads();       // all h stores issued CTA-wide
        if (tid == 0) {
            __threadfence();   // publish h stores device-wide
            const unsigned target = (unsigned)(NCD * (s + 1));
            unsigned arrived = atomicAdd(mycnt, 1u) + 1u;
            if (arrived == target) {
                asm volatile("st.release.gpu.global.u32 [%0], %1;"
                             :: "l"(myflag), "r"((unsigned)(s + 1)) : "memory");
            }
        }

        // off-critical-path stores while tid0 arrives/spins
        if (wid < 2) {
            float2 y2;
            y2.x = hn[0]; y2.y = hn[1];
            *(float2*)(y + ((size_t)t * BB + b0) * 1024 + (size_t)dir * HH + j) = y2;
            y2.x = hn[2]; y2.y = hn[3];
            *(float2*)(y + ((size_t)t * BB + b1) * 1024 + (size_t)dir * HH + j) = y2;
            if (s == TT - 1) {
                float2 q2;
                q2.x = hn[0]; q2.y = hn[1];
                *(float2*)(hid + ((size_t)dir * BB + b0) * HH + j) = q2;
                q2.x = hn[2]; q2.y = hn[3];
                *(float2*)(hid + ((size_t)dir * BB + b1) * HH + j) = q2;
            }
        }

        if (tid == 0) {
            unsigned v;
            do {
                asm volatile("ld.acquire.gpu.global.u32 %0, [%1];"
                             : "=r"(v) : "l"(myflag) : "memory");
            } while (v < (unsigned)(s + 1));
            __threadfence();
        }
        __syncthreads();
    }
}

// ---------------------------------------------------------------------------
// Launch
// ---------------------------------------------------------------------------
extern "C" void kernel_launch(void* const* d_in, const int* in_sizes, int n_in,
                              void* d_out, int out_size)
{
    (void)in_sizes; (void)n_in; (void)out_size;

    const float* x     = (const float*)d_in[0];
    const float* Wih0f = (const float*)d_in[1];
    const float* Whh0f = (const float*)d_in[2];
    const float* bih0f = (const float*)d_in[3];
    const float* bhh0f = (const float*)d_in[4];
    const float* Wih0b = (const float*)d_in[5];
    const float* Whh0b = (const float*)d_in[6];
    const float* bih0b = (const float*)d_in[7];
    const float* bhh0b = (const float*)d_in[8];
    const float* Wih1f = (const float*)d_in[9];
    const float* Whh1f = (const float*)d_in[10];
    const float* bih1f = (const float*)d_in[11];
    const float* bhh1f = (const float*)d_in[12];
    const float* Wih1b = (const float*)d_in[13];
    const float* Whh1b = (const float*)d_in[14];
    const float* bih1b = (const float*)d_in[15];
    const float* bhh1b = (const float*)d_in[16];

    float* out = (float*)d_out;
    const size_t Y_ELEMS = (size_t)TT * BB * 1024;
    float* hid0 = out + Y_ELEMS;
    float* hid1 = out + Y_ELEMS + 2 * BB * HH;

    float* gi = nullptr; cudaGetSymbolAddress((void**)&gi, g_gi);
    float* y0 = nullptr; cudaGetSymbolAddress((void**)&y0, g_y0);
    __nv_bfloat16* hh = nullptr; cudaGetSymbolAddress((void**)&hh, g_hh);
    __nv_bfloat16* hl = nullptr; cudaGetSymbolAddress((void**)&hl, g_hl);
    unsigned* cnt  = nullptr; cudaGetSymbolAddress((void**)&cnt, g_cnt);
    unsigned* flag = nullptr; cudaGetSymbolAddress((void**)&flag, g_flag);
    __nv_bfloat16* wh = nullptr; cudaGetSymbolAddress((void**)&wh, g_wh);
    __nv_bfloat16* wl = nullptr; cudaGetSymbolAddress((void**)&wl, g_wl);
    __nv_bfloat16* xh = nullptr; cudaGetSymbolAddress((void**)&xh, g_xh);
    __nv_bfloat16* xl = nullptr; cudaGetSymbolAddress((void**)&xl, g_xl);

    cudaFuncSetAttribute(gru_layer_mma,
                         cudaFuncAttributeMaxDynamicSharedMemorySize, MMA_SMEM);

    const size_t M = (size_t)TT * BB;            // 16384
    const size_t DIROFF = (size_t)1536 * M;
    const size_t WSLAB = (size_t)1536 * 1024;
    const dim3 ggrid(128, 12);
    const size_t HBYTES = (size_t)2 * 2 * 64 * 32 * 8 * sizeof(__nv_bfloat16);

    // ---------------- layer 0 (K = 512) ----------------
    split_bf16<<<512, 256>>>(Wih0f, wh,          wl,          (size_t)1536 * DD);
    split_bf16<<<512, 256>>>(Wih0b, wh + WSLAB,  wl + WSLAB,  (size_t)1536 * DD);
    split_bf16<<<1024, 256>>>(x,    xh,          xl,          M * DD);

    gemm_bf16_mma<<<ggrid, 256>>>(wh,         wl,         xh, xl, bih0f,
                                  gi,          DD, (int)M);
    gemm_bf16_mma<<<ggrid, 256>>>(wh + WSLAB, wl + WSLAB, xh, xl, bih0b,
                                  gi + DIROFF, DD, (int)M);

    cudaMemsetAsync(hh, 0, HBYTES);
    cudaMemsetAsync(hl, 0, HBYTES);
    cudaMemsetAsync(cnt, 0, 2 * sizeof(unsigned));
    cudaMemsetAsync(flag, 0, 2 * sizeof(unsigned));

    gru_layer_mma<<<128, 256, MMA_SMEM>>>(
        gi, Whh0f, Whh0b, bhh0f, bhh0b, hh, hl, cnt, flag, y0, hid0);

    // ---------------- layer 1 (K = 1024) ----------------
    split_bf16<<<512, 256>>>(Wih1f, wh,          wl,          (size_t)1536 * 1024);
    split_bf16<<<512, 256>>>(Wih1b, wh + WSLAB,  wl + WSLAB,  (size_t)1536 * 1024);
    split_bf16<<<1024, 256>>>(y0,   xh,          xl,          M * 1024);

    gemm_bf16_mma<<<ggrid, 256>>>(wh,         wl,         xh, xl, bih1f,
                                  gi,          1024, (int)M);
    gemm_bf16_mma<<<ggrid, 256>>>(wh + WSLAB, wl + WSLAB, xh, xl, bih1b,
                                  gi + DIROFF, 1024, (int)M);

    cudaMemsetAsync(hh, 0, HBYTES);
    cudaMemsetAsync(hl, 0, HBYTES);
    cudaMemsetAsync(cnt, 0, 2 * sizeof(unsigned));
    cudaMemsetAsync(flag, 0, 2 * sizeof(unsigned));

    gru_layer_mma<<<128, 256, MMA_SMEM>>>(
        gi, Whh1f, Whh1b, bhh1f, bhh1b, hh, hl, cnt, flag, out, hid1);
}

// round 13
// speedup vs baseline: 2.0255x; 1.4533x over previous
#include <cuda_runtime.h>
#include <cuda_bf16.h>
#include <cstdint>
#include <cstddef>

typedef unsigned long long ull;

// Problem constants
#define TT 512
#define BB 32
#define DD 512
#define HH 512

// ---------------------------------------------------------------------------
// Scratch (device globals — no allocations allowed)
// ---------------------------------------------------------------------------
__device__ float g_gi[(size_t)2 * 1536 * (TT * BB)];
__device__ float g_y0[(size_t)TT * BB * 1024];
// hidden state bf16 hi/lo ping-pong: [2 buf][2 dir][32 b][512 k]  (round-8)
__device__ __nv_bfloat16 g_hh[2 * 2 * BB * HH];
__device__ __nv_bfloat16 g_hl[2 * 2 * BB * HH];
__device__ unsigned g_cnt[2];
__device__ unsigned g_flag[2];
__device__ __nv_bfloat16 g_wh[2][1536 * 1024];
__device__ __nv_bfloat16 g_wl[2][1536 * 1024];
__device__ __nv_bfloat16 g_xh[(size_t)16384 * 1024];
__device__ __nv_bfloat16 g_xl[(size_t)16384 * 1024];

// ---------------------------------------------------------------------------
// MMA / ldmatrix macros
// ---------------------------------------------------------------------------
#define MMA_BF16(d, a, b) \
    asm volatile("mma.sync.aligned.m16n8k16.row.col.f32.bf16.bf16.f32 " \
        "{%0,%1,%2,%3}, {%4,%5,%6,%7}, {%8,%9}, {%0,%1,%2,%3};" \
        : "+f"((d)[0]), "+f"((d)[1]), "+f"((d)[2]), "+f"((d)[3]) \
        : "r"((a)[0]), "r"((a)[1]), "r"((a)[2]), "r"((a)[3]), \
          "r"((b)[0]), "r"((b)[1]))

#define LDSM_X4(r, addr) \
    asm volatile("ldmatrix.sync.aligned.m8n8.x4.shared.b16 {%0,%1,%2,%3}, [%4];" \
        : "=r"((r)[0]), "=r"((r)[1]), "=r"((r)[2]), "=r"((r)[3]) : "r"(addr))

#define LDSM_X2(r, addr) \
    asm volatile("ldmatrix.sync.aligned.m8n8.x2.shared.b16 {%0,%1}, [%2];" \
        : "=r"((r)[0]), "=r"((r)[1]) : "r"(addr))

#define CP_ASYNC16(dst, src) \
    asm volatile("cp.async.cg.shared.global [%0], [%1], 16;" \
        :: "r"(dst), "l"(src) : "memory")

// ---------------------------------------------------------------------------
// split fp32 -> bf16 hi + bf16 lo
// ---------------------------------------------------------------------------
__global__ void split_bf16(const float* __restrict__ x,
                           __nv_bfloat16* __restrict__ hi,
                           __nv_bfloat16* __restrict__ lo, size_t n)
{
    size_t i = (size_t)blockIdx.x * blockDim.x + threadIdx.x;
    size_t stride = (size_t)gridDim.x * blockDim.x;
    for (; i < n; i += stride) {
        float v = x[i];
        __nv_bfloat16 h = __float2bfloat16(v);
        hi[i] = h;
        lo[i] = __float2bfloat16(v - __bfloat162float(h));
    }
}

// ---------------------------------------------------------------------------
// bf16 mma.sync GEMM, 3-pass hi/lo split, NOW 2-stage cp.async pipelined.
// C[n][m] = sum_k W[n][k] * X[m][k] + bias[n],  ldc = M = 16384.
// Grid (m_tiles=128, n_tiles), 256 threads (8 warps, 2x4). BK=32.
// Dynamic smem: 2 stages x 4 tiles x 128 x SKW bf16 = 81,920 B.
// ---------------------------------------------------------------------------
#define SKW 40
#define TILE_E (128 * SKW)        // bf16 elems per tile
#define STAGE_E (4 * TILE_E)      // Wh | Wl | Xh | Xl
#define GEMM_SMEM (2 * STAGE_E * 2)

__global__ void __launch_bounds__(256)
gemm_bf16_mma(const __nv_bfloat16* __restrict__ Wh,
              const __nv_bfloat16* __restrict__ Wl,
              const __nv_bfloat16* __restrict__ Xh,
              const __nv_bfloat16* __restrict__ Xl,
              const float* __restrict__ bias,
              float* __restrict__ C, int K, int ldc)
{
    extern __shared__ __align__(16) __nv_bfloat16 sm[];

    const int tid  = threadIdx.x;
    const int wid  = tid >> 5;
    const int lane = tid & 31;
    const int m0   = blockIdx.x * 128;
    const int n0   = blockIdx.y * 128;
    const int wn   = wid >> 2;
    const int wm   = wid & 3;

    float acc[4][4][4];
#pragma unroll
    for (int nt = 0; nt < 4; nt++)
#pragma unroll
        for (int mt = 0; mt < 4; mt++)
#pragma unroll
            for (int e = 0; e < 4; e++) acc[nt][mt][e] = 0.0f;

    // stage-0 ldmatrix base addresses (bytes); add stage offset per iter
    const int a_off = (wn * 64 + (lane & 15)) * SKW + (lane >> 4) * 8;
    const int b_off = (wm * 32 + (lane & 7)) * SKW + ((lane >> 3) & 1) * 8;
    const uint32_t aWh0 = (uint32_t)__cvta_generic_to_shared(sm + a_off);
    const uint32_t aWl0 = aWh0 + TILE_E * 2;
    const uint32_t aXh0 = (uint32_t)__cvta_generic_to_shared(sm + 2 * TILE_E + b_off);
    const uint32_t aXl0 = aXh0 + TILE_E * 2;

    // staging geometry: per tile 512 16B-chunks; thread does chunks tid, tid+256
    const int srow0 = tid >> 2, sc0 = tid & 3;
    const int srow1 = (tid + 256) >> 2, sc1 = (tid + 256) & 3;
    const uint32_t d00 = (uint32_t)__cvta_generic_to_shared(sm + srow0 * SKW + sc0 * 8);
    const uint32_t d01 = (uint32_t)__cvta_generic_to_shared(sm + srow1 * SKW + sc1 * 8);

    const int nk = K >> 5;

    // prologue: stage 0 of k-tile 0
    {
        const size_t gw0 = (size_t)(n0 + srow0) * K + sc0 * 8;
        const size_t gw1 = (size_t)(n0 + srow1) * K + sc1 * 8;
        const size_t gx0 = (size_t)(m0 + srow0) * K + sc0 * 8;
        const size_t gx1 = (size_t)(m0 + srow1) * K + sc1 * 8;
        CP_ASYNC16(d00,                  Wh + gw0);
        CP_ASYNC16(d00 + TILE_E * 2,     Wl + gw0);
        CP_ASYNC16(d00 + 2 * TILE_E * 2, Xh + gx0);
        CP_ASYNC16(d00 + 3 * TILE_E * 2, Xl + gx0);
        CP_ASYNC16(d01,                  Wh + gw1);
        CP_ASYNC16(d01 + TILE_E * 2,     Wl + gw1);
        CP_ASYNC16(d01 + 2 * TILE_E * 2, Xh + gx1);
        CP_ASYNC16(d01 + 3 * TILE_E * 2, Xl + gx1);
        asm volatile("cp.async.commit_group;" ::: "memory");
    }

    for (int kt = 0; kt < nk; kt++) {
        const uint32_t stB = (uint32_t)((kt & 1) * STAGE_E * 2);

        if (kt + 1 < nk) {
            // prefetch next k-tile into the other stage
            const uint32_t nsB = (uint32_t)(((kt + 1) & 1) * STAGE_E * 2);
            const int k0n = (kt + 1) * 32;
            const size_t gw0 = (size_t)(n0 + srow0) * K + k0n + sc0 * 8;
            const size_t gw1 = (size_t)(n0 + srow1) * K + k0n + sc1 * 8;
            const size_t gx0 = (size_t)(m0 + srow0) * K + k0n + sc0 * 8;
            const size_t gx1 = (size_t)(m0 + srow1) * K + k0n + sc1 * 8;
            CP_ASYNC16(d00 + nsB,                  Wh + gw0);
            CP_ASYNC16(d00 + nsB + TILE_E * 2,     Wl + gw0);
            CP_ASYNC16(d00 + nsB + 2 * TILE_E * 2, Xh + gx0);
            CP_ASYNC16(d00 + nsB + 3 * TILE_E * 2, Xl + gx0);
            CP_ASYNC16(d01 + nsB,                  Wh + gw1);
            CP_ASYNC16(d01 + nsB + TILE_E * 2,     Wl + gw1);
            CP_ASYNC16(d01 + nsB + 2 * TILE_E * 2, Xh + gx1);
            CP_ASYNC16(d01 + nsB + 3 * TILE_E * 2, Xl + gx1);
            asm volatile("cp.async.commit_group;" ::: "memory");
            asm volatile("cp.async.wait_group 1;" ::: "memory");
        } else {
            asm volatile("cp.async.wait_group 0;" ::: "memory");
        }
        __syncthreads();

#pragma unroll
        for (int kk = 0; kk < 2; kk++) {
            const uint32_t koff = stB + (uint32_t)(kk * 32);
            uint32_t ah[4][4], al[4][4], bh[4][2], bl[4][2];
#pragma unroll
            for (int nt = 0; nt < 4; nt++) {
                const uint32_t ro = (uint32_t)(nt * 16 * SKW * 2);
                LDSM_X4(ah[nt], aWh0 + ro + koff);
                LDSM_X4(al[nt], aWl0 + ro + koff);
            }
#pragma unroll
            for (int mt = 0; mt < 4; mt++) {
                const uint32_t ro = (uint32_t)(mt * 8 * SKW * 2);
                LDSM_X2(bh[mt], aXh0 + ro + koff);
                LDSM_X2(bl[mt], aXl0 + ro + koff);
            }
#pragma unroll
            for (int nt = 0; nt < 4; nt++)
#pragma unroll
                for (int mt = 0; mt < 4; mt++) {
                    MMA_BF16(acc[nt][mt], ah[nt], bh[mt]);
                    MMA_BF16(acc[nt][mt], ah[nt], bl[mt]);
                    MMA_BF16(acc[nt][mt], al[nt], bh[mt]);
                }
        }
        __syncthreads();
    }

    const int r0 = lane >> 2;
    const int c0 = (lane & 3) * 2;
#pragma unroll
    for (int nt = 0; nt < 4; nt++) {
        const int nbase = n0 + wn * 64 + nt * 16;
        const float b0 = bias[nbase + r0];
        const float b1 = bias[nbase + 8 + r0];
#pragma unroll
        for (int mt = 0; mt < 4; mt++) {
            const int mbase = m0 + wm * 32 + mt * 8;
            float2 v0, v1;
            v0.x = acc[nt][mt][0] + b0; v0.y = acc[nt][mt][1] + b0;
            v1.x = acc[nt][mt][2] + b1; v1.y = acc[nt][mt][3] + b1;
            *(float2*)(C + (size_t)(nbase + r0) * ldc + mbase + c0) = v0;
            *(float2*)(C + (size_t)(nbase + 8 + r0) * ldc + mbase + c0) = v1;
        }
    }
}

// ---------------------------------------------------------------------------
// Persistent MMA GRU — EXACT round-8 engine (best measured: 5.1 us/step),
// with ONE change: y/hid stores moved after the flag release (off-path).
// Grid: 128 CTAs = 2 dirs x 64 j-blocks (8 j each). 128 threads (4 warps).
// Warp w owns K-quarter (8 ktiles); B frags in 96 regs, loaded once.
// SMEM: A 66,560 B + red[4][2][3][32][4]f 12,288 B = 78,848 B.
// ---------------------------------------------------------------------------
#define RS 520
#define NCD 64
#define A_ELEMS (32 * RS)
#define RED_OFF (2 * A_ELEMS * 2)
#define MMA_SMEM (RED_OFF + 4 * 2 * 3 * 32 * 16)

__global__ __launch_bounds__(128, 1)
void gru_layer_mma(const float* __restrict__ gi,
                   const float* __restrict__ Whh_f,
                   const float* __restrict__ Whh_b,
                   const float* __restrict__ bhh_f,
                   const float* __restrict__ bhh_b,
                   __nv_bfloat16* __restrict__ hh,   // [2][2][32][512]
                   __nv_bfloat16* __restrict__ hl,
                   unsigned* __restrict__ cnt,
                   unsigned* __restrict__ flag,
                   float* __restrict__ y,
                   float* __restrict__ hid)
{
    extern __shared__ __align__(16) char smraw[];
    __nv_bfloat16* sAh = (__nv_bfloat16*)smraw;
    __nv_bfloat16* sAl = sAh + A_ELEMS;
    float* red = (float*)(smraw + RED_OFF);

    __nv_bfloat16* sWh = sAh;
    __nv_bfloat16* sWl = sAh + 24 * RS;

    const int tid  = threadIdx.x;
    const int wid  = tid >> 5;
    const int lane = tid & 31;
    const int dir  = (int)(blockIdx.x >> 6);
    const int j0   = (int)(blockIdx.x & 63) * 8;

    const float* Whh = dir ? Whh_b : Whh_f;
    const float* bhh = dir ? bhh_b : bhh_f;

    // ---- stage Whh tile (24 rows x 512) hi/lo split into smem ----
    for (int i = tid; i < 24 * 128; i += 128) {
        int rr = i >> 7;
        int c4 = i & 127;
        int g = rr >> 3, jj = rr & 7;
        int grow = g * 512 + j0 + jj;
        float4 v = *(const float4*)(Whh + (size_t)grow * 512 + c4 * 4);
        int so = rr * RS + c4 * 4;
        float vv[4] = {v.x, v.y, v.z, v.w};
#pragma unroll
        for (int e = 0; e < 4; e++) {
            __nv_bfloat16 h = __float2bfloat16(vv[e]);
            sWh[so + e] = h;
            sWl[so + e] = __float2bfloat16(vv[e] - __bfloat162float(h));
        }
    }
    __syncthreads();

    // ---- hoist B fragments into registers: [8 kt][3 g][hi/lo][2] ----
    uint32_t bh[8][3][2], bl[8][3][2];
    {
        const int brow = (lane & 7);
        const int bcol = ((lane >> 3) & 1) * 8;
#pragma unroll
        for (int kt = 0; kt < 8; kt++) {
            const uint32_t koff = (uint32_t)((wid * 8 + kt) * 16 * 2);
#pragma unroll
            for (int g = 0; g < 3; g++) {
                uint32_t ah_ = (uint32_t)__cvta_generic_to_shared(
                    sWh + (g * 8 + brow) * RS + bcol) + koff;
                uint32_t al_ = (uint32_t)__cvta_generic_to_shared(
                    sWl + (g * 8 + brow) * RS + bcol) + koff;
                LDSM_X2(bh[kt][g], ah_);
                LDSM_X2(bl[kt][g], al_);
            }
        }
    }
    __syncthreads();

    uint32_t aAh[2], aAl[2];
#pragma unroll
    for (int mt = 0; mt < 2; mt++) {
        const int arow = mt * 16 + (lane & 15);
        const int acol = (lane >> 4) * 8;
        aAh[mt] = (uint32_t)__cvta_generic_to_shared(sAh + arow * RS + acol);
        aAl[mt] = (uint32_t)__cvta_generic_to_shared(sAl + arow * RS + acol);
    }

    const int gm  = wid;
    const int b0  = gm * 16 + (lane >> 2);
    const int b1  = b0 + 8;
    const int j   = j0 + 2 * (lane & 3);

    const float br0 = bhh[j],          br1 = bhh[j + 1];
    const float bz0 = bhh[HH + j],     bz1 = bhh[HH + j + 1];
    const float bn0 = bhh[2 * HH + j], bn1 = bhh[2 * HH + j + 1];

    const float* gb[3][2];
#pragma unroll
    for (int g = 0; g < 3; g++) {
#pragma unroll
        for (int q = 0; q < 2; q++)
            gb[g][q] = gi + ((size_t)dir * 1536 + g * 512 + j + q) * (size_t)(TT * BB);
    }

    unsigned* mycnt  = cnt + dir;
    unsigned* myflag = flag + dir;

    float hp[4] = {0.0f, 0.0f, 0.0f, 0.0f};

    for (int s = 0; s < TT; s++) {
        const int t = dir ? (TT - 1 - s) : s;

        // ---- stage h hi/lo for this step: 32 rows x 512 bf16 each ----
        {
            const uint4* srch = (const uint4*)(hh + ((size_t)(s & 1) * 2 + dir) * (BB * HH));
            const uint4* srcl = (const uint4*)(hl + ((size_t)(s & 1) * 2 + dir) * (BB * HH));
#pragma unroll
            for (int i = 0; i < 16; i++) {
                int idx = tid + i * 128;
                int row = idx >> 6;
                int c8  = idx & 63;
                uint4 vh = __ldcg(srch + idx);
                uint4 vl = __ldcg(srcl + idx);
                *(uint4*)(sAh + row * RS + c8 * 8) = vh;
                *(uint4*)(sAl + row * RS + c8 * 8) = vl;
            }
        }
        __syncthreads();

        // ---- gi prefetch (warps 0/1) ----
        float pre[3][4];
        if (wid < 2) {
#pragma unroll
            for (int g = 0; g < 3; g++) {
                pre[g][0] = __ldcg(gb[g][0] + t * BB + b0);
                pre[g][1] = __ldcg(gb[g][1] + t * BB + b0);
                pre[g][2] = __ldcg(gb[g][0] + t * BB + b1);
                pre[g][3] = __ldcg(gb[g][1] + t * BB + b1);
            }
        }

        // ---- MMA over this warp's 8 ktiles ----
        float acc[2][3][4];
#pragma unroll
        for (int mt = 0; mt < 2; mt++)
#pragma unroll
            for (int g = 0; g < 3; g++)
#pragma unroll
                for (int e = 0; e < 4; e++) acc[mt][g][e] = 0.0f;

#pragma unroll
        for (int kt = 0; kt < 8; kt++) {
            const uint32_t koff = (uint32_t)((wid * 8 + kt) * 32);
#pragma unroll
            for (int mt = 0; mt < 2; mt++) {
                uint32_t ah[4], al[4];
                LDSM_X4(ah, aAh[mt] + koff);
                LDSM_X4(al, aAl[mt] + koff);
#pragma unroll
                for (int g = 0; g < 3; g++) {
                    MMA_BF16(acc[mt][g], ah, bh[kt][g]);
                    MMA_BF16(acc[mt][g], ah, bl[kt][g]);
                    MMA_BF16(acc[mt][g], al, bh[kt][g]);
                }
            }
        }

        // ---- cross-warp K-reduction via smem ----
#pragma unroll
        for (int mt = 0; mt < 2; mt++)
#pragma unroll
            for (int g = 0; g < 3; g++) {
                float4 v;
                v.x = acc[mt][g][0]; v.y = acc[mt][g][1];
                v.z = acc[mt][g][2]; v.w = acc[mt][g][3];
                *(float4*)(red + (((wid * 2 + mt) * 3 + g) * 32 + lane) * 4) = v;
            }
        __syncthreads();

        // ---- gates + h publish (warps 0/1, m-tile = wid) ----
        float hn[4];
        if (wid < 2) {
            float tot[3][4];
#pragma unroll
            for (int g = 0; g < 3; g++) {
                float4 v0 = *(float4*)(red + (((0 * 2 + gm) * 3 + g) * 32 + lane) * 4);
                float4 v1 = *(float4*)(red + (((1 * 2 + gm) * 3 + g) * 32 + lane) * 4);
                float4 v2 = *(float4*)(red + (((2 * 2 + gm) * 3 + g) * 32 + lane) * 4);
                float4 v3 = *(float4*)(red + (((3 * 2 + gm) * 3 + g) * 32 + lane) * 4);
                tot[g][0] = ((v0.x + v1.x) + (v2.x + v3.x));
                tot[g][1] = ((v0.y + v1.y) + (v2.y + v3.y));
                tot[g][2] = ((v0.z + v1.z) + (v2.z + v3.z));
                tot[g][3] = ((v0.w + v1.w) + (v2.w + v3.w));
            }

            const float brj[2] = {br0, br1}, bzj[2] = {bz0, bz1}, bnj[2] = {bn0, bn1};
#pragma unroll
            for (int c = 0; c < 4; c++) {
                const int q = c & 1;
                const float ar = tot[0][c] + brj[q];
                const float az = tot[1][c] + bzj[q];
                const float an = tot[2][c] + bnj[q];
                const float r = 1.0f / (1.0f + expf(-(pre[0][c] + ar)));
                const float z = 1.0f / (1.0f + expf(-(pre[1][c] + az)));
                const float n = tanhf(pre[2][c] + r * an);
                hn[c] = (1.0f - z) * n + z * hp[c];
                hp[c] = hn[c];
            }

            // publish h (bf16 hi/lo, ping-pong) — critical path
            const size_t ob = ((size_t)((s + 1) & 1) * 2 + dir) * (BB * HH);
            __nv_bfloat162 h2, l2;
            h2.x = __float2bfloat16(hn[0]);
            h2.y = __float2bfloat16(hn[1]);
            l2.x = __float2bfloat16(hn[0] - __bfloat162float(h2.x));
            l2.y = __float2bfloat16(hn[1] - __bfloat162float(h2.y));
            *(__nv_bfloat162*)(hh + ob + (size_t)b0 * HH + j) = h2;
            *(__nv_bfloat162*)(hl + ob + (size_t)b0 * HH + j) = l2;
            h2.x = __float2bfloat16(hn[2]);
            h2.y = __float2bfloat16(hn[3]);
            l2.x = __float2bfloat16(hn[2] - __bfloat162float(h2.x));
            l2.y = __float2bfloat16(hn[3] - __bfloat162float(h2.y));
            *(__nv_bfloat162*)(hh + ob + (size_t)b1 * HH + j) = h2;
            *(__nv_bfloat162*)(hl + ob + (size_t)b1 * HH + j) = l2;
        }

        // ---- per-direction global barrier (round-8 proven) ----
        __syncthreads();
        if (tid == 0) {
            __threadfence();
            const unsigned target = (unsigned)(NCD * (s + 1));
            unsigned arrived = atomicAdd(mycnt, 1u) + 1u;
            if (arrived == target) {
                asm volatile("st.release.gpu.global.u32 [%0], %1;"
                             :: "l"(myflag), "r"((unsigned)(s + 1)) : "memory");
            }
        }

        // off-critical-path y/hid stores while tid0 arrives/spins
        if (wid < 2) {
            float2 y2;
            y2.x = hn[0]; y2.y = hn[1];
            *(float2*)(y + ((size_t)t * BB + b0) * 1024 + (size_t)dir * HH + j) = y2;
            y2.x = hn[2]; y2.y = hn[3];
            *(float2*)(y + ((size_t)t * BB + b1) * 1024 + (size_t)dir * HH + j) = y2;
            if (s == TT - 1) {
                float2 q2;
                q2.x = hn[0]; q2.y = hn[1];
                *(float2*)(hid + ((size_t)dir * BB + b0) * HH + j) = q2;
                q2.x = hn[2]; q2.y = hn[3];
                *(float2*)(hid + ((size_t)dir * BB + b1) * HH + j) = q2;
            }
        }

        if (tid == 0) {
            unsigned v;
            do {
                asm volatile("ld.acquire.gpu.global.u32 %0, [%1];"
                             : "=r"(v) : "l"(myflag) : "memory");
            } while (v < (unsigned)(s + 1));
            __threadfence();
        }
        __syncthreads();
    }
}

// ---------------------------------------------------------------------------
// Launch
// ---------------------------------------------------------------------------
extern "C" void kernel_launch(void* const* d_in, const int* in_sizes, int n_in,
                              void* d_out, int out_size)
{
    (void)in_sizes; (void)n_in; (void)out_size;

    const float* x     = (const float*)d_in[0];
    const float* Wih0f = (const float*)d_in[1];
    const float* Whh0f = (const float*)d_in[2];
    const float* bih0f = (const float*)d_in[3];
    const float* bhh0f = (const float*)d_in[4];
    const float* Wih0b = (const float*)d_in[5];
    const float* Whh0b = (const float*)d_in[6];
    const float* bih0b = (const float*)d_in[7];
    const float* bhh0b = (const float*)d_in[8];
    const float* Wih1f = (const float*)d_in[9];
    const float* Whh1f = (const float*)d_in[10];
    const float* bih1f = (const float*)d_in[11];
    const float* bhh1f = (const float*)d_in[12];
    const float* Wih1b = (const float*)d_in[13];
    const float* Whh1b = (const float*)d_in[14];
    const float* bih1b = (const float*)d_in[15];
    const float* bhh1b = (const float*)d_in[16];

    float* out = (float*)d_out;
    const size_t Y_ELEMS = (size_t)TT * BB * 1024;
    float* hid0 = out + Y_ELEMS;
    float* hid1 = out + Y_ELEMS + 2 * BB * HH;

    float* gi = nullptr; cudaGetSymbolAddress((void**)&gi, g_gi);
    float* y0 = nullptr; cudaGetSymbolAddress((void**)&y0, g_y0);
    __nv_bfloat16* hh = nullptr; cudaGetSymbolAddress((void**)&hh, g_hh);
    __nv_bfloat16* hl = nullptr; cudaGetSymbolAddress((void**)&hl, g_hl);
    unsigned* cnt  = nullptr; cudaGetSymbolAddress((void**)&cnt, g_cnt);
    unsigned* flag = nullptr; cudaGetSymbolAddress((void**)&flag, g_flag);
    __nv_bfloat16* wh = nullptr; cudaGetSymbolAddress((void**)&wh, g_wh);
    __nv_bfloat16* wl = nullptr; cudaGetSymbolAddress((void**)&wl, g_wl);
    __nv_bfloat16* xh = nullptr; cudaGetSymbolAddress((void**)&xh, g_xh);
    __nv_bfloat16* xl = nullptr; cudaGetSymbolAddress((void**)&xl, g_xl);

    cudaFuncSetAttribute(gru_layer_mma,
                         cudaFuncAttributeMaxDynamicSharedMemorySize, MMA_SMEM);
    cudaFuncSetAttribute(gemm_bf16_mma,
                         cudaFuncAttributeMaxDynamicSharedMemorySize, GEMM_SMEM);

    const size_t M = (size_t)TT * BB;            // 16384
    const size_t DIROFF = (size_t)1536 * M;
    const size_t WSLAB = (size_t)1536 * 1024;
    const dim3 ggrid(128, 12);
    const size_t HBYTES = (size_t)2 * 2 * BB * HH * sizeof(__nv_bfloat16);

    // ---------------- layer 0 (K = 512) ----------------
    split_bf16<<<512, 256>>>(Wih0f, wh,          wl,          (size_t)1536 * DD);
    split_bf16<<<512, 256>>>(Wih0b, wh + WSLAB,  wl + WSLAB,  (size_t)1536 * DD);
    split_bf16<<<1024, 256>>>(x,    xh,          xl,          M * DD);

    gemm_bf16_mma<<<ggrid, 256, GEMM_SMEM>>>(wh,         wl,         xh, xl, bih0f,
                                             gi,          DD, (int)M);
    gemm_bf16_mma<<<ggrid, 256, GEMM_SMEM>>>(wh + WSLAB, wl + WSLAB, xh, xl, bih0b,
                                             gi + DIROFF, DD, (int)M);

    cudaMemsetAsync(hh, 0, HBYTES);
    cudaMemsetAsync(hl, 0, HBYTES);
    cudaMemsetAsync(cnt, 0, 2 * sizeof(unsigned));
    cudaMemsetAsync(flag, 0, 2 * sizeof(unsigned));

    gru_layer_mma<<<128, 128, MMA_SMEM>>>(
        gi, Whh0f, Whh0b, bhh0f, bhh0b, hh, hl, cnt, flag, y0, hid0);

    // ---------------- layer 1 (K = 1024) ----------------
    split_bf16<<<512, 256>>>(Wih1f, wh,          wl,          (size_t)1536 * 1024);
    split_bf16<<<512, 256>>>(Wih1b, wh + WSLAB,  wl + WSLAB,  (size_t)1536 * 1024);
    split_bf16<<<1024, 256>>>(y0,   xh,          xl,          M * 1024);

    gemm_bf16_mma<<<ggrid, 256, GEMM_SMEM>>>(wh,         wl,         xh, xl, bih1f,
                                             gi,          1024, (int)M);
    gemm_bf16_mma<<<ggrid, 256, GEMM_SMEM>>>(wh + WSLAB, wl + WSLAB, xh, xl, bih1b,
                                             gi + DIROFF, 1024, (int)M);

    cudaMemsetAsync(hh, 0, HBYTES);
    cudaMemsetAsync(hl, 0, HBYTES);
    cudaMemsetAsync(cnt, 0, 2 * sizeof(unsigned));
    cudaMemsetAsync(flag, 0, 2 * sizeof(unsigned));

    gru_layer_mma<<<128, 128, MMA_SMEM>>>(
        gi, Whh1f, Whh1b, bhh1f, bhh1b, hh, hl, cnt, flag, out, hid1);
}